// round 8
// baseline (speedup 1.0000x reference)
#include <cuda_runtime.h>
#include <cstdint>

// ---------------------------------------------------------------------------
// TorchNeighborList: N=4096 atoms, no PBC. Output layout (as float32):
//   [0,      M)   idx_i   (valid prefix [0,T), sentinel N in [T,M))
//   [M,     2M)   idx_j   (same split)
//   [2M,    5M)   Rij     (valid prefix [0,3T), zeros after)
//   [5M,    8M)   cell_offset (all zeros)
//   [8M,    9M)   mask    (1.0 in [0,T), 0.0 after)
//   [9M]          num_pairs = T
// where M = 2P = N*(N-1), T = number of in-cutoff directed pairs (~325k).
//
// Ordering reproduced analytically: centers ascending; within center k,
// neighbors in order j = (k+t) mod N for t = 1..N-1 (exactly the reference's
// stable argsort over concat(triu_i, triu_j)).
//
// Schedule:
//   L1 fused : sentinel-fill blocks | zero-fill blocks | count blocks
//              (branch-free store streams; counts cache validity ballots)
//   L2 scan  : coalesced shfl-based exclusive scan -> g_offsets, T
//   L3 emit  : warp-per-segment, lane-per-valid-entry (shfl prefix-popc,
//              no dependent-load chains), coalesced compacted stores
// ---------------------------------------------------------------------------

#define CHUNK 512
#define MPW   (CHUNK / 32)          // ballots per segment (16)
#define MAX_SEG 65536

__device__ int g_counts[MAX_SEG];
__device__ int g_offsets[MAX_SEG];
__device__ unsigned g_masks[MAX_SEG * MPW];
__device__ int g_total;

// exact (non-contracted) squared distance, matching jnp.linalg.norm assoc order
__device__ __forceinline__ float dist2(float dx, float dy, float dz) {
    return __fadd_rn(__fadd_rn(__fmul_rn(dx, dx), __fmul_rn(dy, dy)),
                     __fmul_rn(dz, dz));
}

// -------- Kernel 1: region-split default fill || counts -------------------
// Blocks [0, FS):   sentinel fill over [0, 2M)
// Blocks [FS, FB):  zero fill over [2M, 9M)
// Blocks [FB, ...): warp-per-(center,chunk) counts + ballot cache
__global__ __launch_bounds__(256) void fill_count_kernel(
    const float* __restrict__ pos, float* __restrict__ out,
    size_t M, int N, int C, int FS, int FB) {
    int b = (int)blockIdx.x;
    if (b < FB) {
        float4* __restrict__ out4 = (float4*)out;
        float4 v;
        size_t lo4, hi4, stride, start;
        if (b < FS) {
            const float sn = (float)N;
            v = make_float4(sn, sn, sn, sn);
            lo4 = 0;
            hi4 = (2 * M) / 4;
            stride = (size_t)FS * 256;
            start = (size_t)b * 256 + threadIdx.x;
        } else {
            v = make_float4(0.f, 0.f, 0.f, 0.f);
            lo4 = (2 * M) / 4;
            hi4 = (9 * M) / 4;
            stride = (size_t)(FB - FS) * 256;
            start = lo4 + (size_t)(b - FS) * 256 + threadIdx.x;
        }
        // branch-free 2-wide store stream
        size_t i = start;
        for (; i + stride < hi4; i += 2 * stride) {
            out4[i] = v;
            out4[i + stride] = v;
        }
        if (i < hi4) out4[i] = v;
    } else {
        // ---- counts + ballot cache: warp per (center,chunk) ----
        int warp = (int)((((size_t)b - FB) * blockDim.x + threadIdx.x) >> 5);
        int lane = threadIdx.x & 31;
        if (warp >= N * C) return;
        int k = warp / C;
        int c = warp - k * C;

        const float* pk = pos + 3 * (size_t)k;
        float xk = __ldg(pk), yk = __ldg(pk + 1), zk = __ldg(pk + 2);

        int cnt = 0;
        int tbase = c * CHUNK;
#pragma unroll 4
        for (int u = 0; u < MPW; u++) {
            int t = tbase + u * 32 + lane;
            bool valid = false;
            if (t > 0 && t < N) {
                int j = k + t;
                if (j >= N) j -= N;
                const float* pj = pos + 3 * (size_t)j;
                float dx = __fsub_rn(__ldg(pj),     xk);
                float dy = __fsub_rn(__ldg(pj + 1), yk);
                float dz = __fsub_rn(__ldg(pj + 2), zk);
                valid = dist2(dx, dy, dz) < 25.0f;
            }
            unsigned m = __ballot_sync(0xffffffffu, valid);
            if (lane == 0) g_masks[warp * MPW + u] = m;
            cnt += __popc(m);
        }
        if (lane == 0) g_counts[warp] = cnt;
    }
}

// -------- Kernel 2: coalesced exclusive scan (1024 thr, shfl) -------------
__global__ __launch_bounds__(1024) void scan_kernel(float* __restrict__ out,
                                                    size_t M, int S) {
    __shared__ int wsum[32];
    __shared__ int wbase[32];
    __shared__ int s_tile_total;
    int t = threadIdx.x;
    int warp = t >> 5, lane = t & 31;
    int running = 0;

    for (int tile = 0; tile < S; tile += 1024) {
        int i = tile + t;
        int c = (i < S) ? g_counts[i] : 0;

        int incl = c;
#pragma unroll
        for (int o = 1; o < 32; o <<= 1) {
            int v = __shfl_up_sync(0xffffffffu, incl, o);
            if (lane >= o) incl += v;
        }
        if (lane == 31) wsum[warp] = incl;
        __syncthreads();

        if (warp == 0) {
            int v = wsum[lane];
            int winc = v;
#pragma unroll
            for (int o = 1; o < 32; o <<= 1) {
                int x = __shfl_up_sync(0xffffffffu, winc, o);
                if (lane >= o) winc += x;
            }
            wbase[lane] = winc - v;
            if (lane == 31) s_tile_total = winc;
        }
        __syncthreads();

        if (i < S) g_offsets[i] = running + wbase[warp] + (incl - c);
        running += s_tile_total;
        __syncthreads();
    }
    if (t == 0) {
        g_total = running;
        out[9 * M] = (float)running;  // num_pairs
    }
}

// -------- Kernel 3: warp-per-segment, lane-per-valid-entry emit -----------
__global__ __launch_bounds__(256) void emit_kernel(const float* __restrict__ pos,
                                                   float* __restrict__ out,
                                                   size_t M, int N, int C) {
    int w = (int)((blockIdx.x * (size_t)blockDim.x + threadIdx.x) >> 5);
    int lane = threadIdx.x & 31;
    if (w >= N * C) return;
    int k = w / C;
    int c = w - k * C;

    // parallel ballot load (lanes 0..15) + prefix popcount via shfl
    unsigned m = g_masks[w * MPW + (lane & 15)];
    int pc = (lane < 16) ? __popc(m) : 0;
    int cum = pc;
#pragma unroll
    for (int o = 1; o < 32; o <<= 1) {
        int v = __shfl_up_sync(0xffffffffu, cum, o);
        if (lane >= o) cum += v;
    }
    int cnt = __shfl_sync(0xffffffffu, cum, 15);
    if (cnt == 0) return;

    int base = g_offsets[w];
    const float* pk = pos + 3 * (size_t)k;
    float xk = __ldg(pk), yk = __ldg(pk + 1), zk = __ldg(pk + 2);
    float fk = (float)k;

    float* __restrict__ idx_i = out;
    float* __restrict__ idx_j = out + M;
    float* __restrict__ rij   = out + 2 * M;
    float* __restrict__ maskp = out + 8 * M;

    for (int r0 = 0; r0 < cnt; r0 += 32) {
        int r = r0 + lane;
        // locate ballot containing rank r: usel = #ballots with cum <= r
        int usel = 0, prev = 0;
#pragma unroll
        for (int u = 0; u < MPW; u++) {
            int cu = __shfl_sync(0xffffffffu, cum, u);
            if (r >= cu) { usel = u + 1; prev = cu; }
        }
        unsigned mm = __shfl_sync(0xffffffffu, m, usel & 31);
        int rr = r - prev;
        for (int q = 0; q < rr; q++) mm &= mm - 1;  // drop rr lowest bits
        int bit = __ffs(mm) - 1;

        if (r < cnt) {
            int t = c * CHUNK + usel * 32 + bit;
            int j = k + t;
            if (j >= N) j -= N;
            const float* pj = pos + 3 * (size_t)j;
            float dx = __fsub_rn(__ldg(pj),     xk);   // pos[j]-pos[k]
            float dy = __fsub_rn(__ldg(pj + 1), yk);
            float dz = __fsub_rn(__ldg(pj + 2), zk);
            int p = base + r;
            idx_i[p] = fk;
            idx_j[p] = (float)j;
            rij[3 * (size_t)p + 0] = dx;
            rij[3 * (size_t)p + 1] = dy;
            rij[3 * (size_t)p + 2] = dz;
            maskp[p] = 1.0f;
        }
    }
}

// ---------------------------------------------------------------------------
extern "C" void kernel_launch(void* const* d_in, const int* in_sizes, int n_in,
                              void* d_out, int out_size) {
    const float* pos = (const float*)d_in[0];
    int N = in_sizes[0] / 3;                   // 4096
    size_t M = ((size_t)out_size - 1) / 9;     // 2P = N*(N-1)
    float* out = (float*)d_out;

    int C = (N + CHUNK - 1) / CHUNK;           // 8 chunks per center
    int S = N * C;                             // 32768 segments

    int count_blocks = (S * 32 + 255) / 256;   // 4096: warp per segment
    int FS = 1052;                             // sentinel fill (2/9 of bytes)
    int FB = 4736;                             // total fill blocks

    fill_count_kernel<<<FB + count_blocks, 256>>>(pos, out, M, N, C, FS, FB);
    scan_kernel<<<1, 1024>>>(out, M, S);
    emit_kernel<<<(S * 32 + 255) / 256, 256>>>(pos, out, M, N, C);
}

// round 9
// speedup vs baseline: 1.0914x; 1.0914x over previous
#include <cuda_runtime.h>
#include <cstdint>

// ---------------------------------------------------------------------------
// TorchNeighborList: N=4096 atoms, no PBC. Output layout (as float32):
//   [0,      M)   idx_i   (valid prefix [0,T), sentinel N in [T,M))
//   [M,     2M)   idx_j   (same split)
//   [2M,    5M)   Rij     (valid prefix [0,3T), zeros after)
//   [5M,    8M)   cell_offset (all zeros)
//   [8M,    9M)   mask    (1.0 in [0,T), 0.0 after)
//   [9M]          num_pairs = T
// where M = 2P = N*(N-1), T = number of in-cutoff directed pairs (~325k).
//
// Ordering reproduced analytically: centers ascending; within center k,
// neighbors in order j = (k+t) mod N for t = 1..N-1 (exactly the reference's
// stable argsort over concat(triu_i, triu_j)).
//
// Schedule:
//   L1 fused : blocks [0,FB) uniform default fill; blocks [FB,+4K) counts
//              (warp per (center,chunk)) + validity-ballot cache
//   L2 scan  : single block, ALL counts prefetched into registers first
//              (one latency exposure), then register/shfl tile scans
//   L3 emit  : thread-per-valid-pair (binary search segment, nth bit of
//              cached ballot) -> coalesced compacted stores at [0,T)
// ---------------------------------------------------------------------------

#define CHUNK 512
#define MPW   (CHUNK / 32)          // ballots per segment (16)
#define MAX_SEG 65536
#define NTILES 32                   // S / 1024 for N=4096

__device__ int g_counts[MAX_SEG];
__device__ int g_offsets[MAX_SEG];
__device__ unsigned g_masks[MAX_SEG * MPW];
__device__ int g_total;

// exact (non-contracted) squared distance, matching jnp.linalg.norm assoc order
__device__ __forceinline__ float dist2(float dx, float dy, float dz) {
    return __fadd_rn(__fadd_rn(__fmul_rn(dx, dx), __fmul_rn(dy, dy)),
                     __fmul_rn(dz, dz));
}

// -------- Kernel 1: uniform default fill || counts ------------------------
__global__ __launch_bounds__(256) void fill_count_kernel(
    const float* __restrict__ pos, float* __restrict__ out,
    size_t M, int N, int C, int FB) {
    if ((int)blockIdx.x < FB) {
        // ---- uniform fill: sentinel over [0,2M), zero over [2M,9M) ----
        float4* __restrict__ out4 = (float4*)out;
        const float sn = (float)N;
        const float4 sv = make_float4(sn, sn, sn, sn);
        const float4 zv = make_float4(0.f, 0.f, 0.f, 0.f);
        size_t n4 = (9 * M) / 4;
        size_t idx_end4 = (2 * M) / 4;
        size_t stride = (size_t)FB * 512;           // 2 vec4 per thread/iter
        size_t base = (size_t)blockIdx.x * 512 + threadIdx.x;
        for (size_t i = base; i < n4; i += stride) {
            out4[i] = (i < idx_end4) ? sv : zv;
            size_t i2 = i + 256;
            if (i2 < n4) out4[i2] = (i2 < idx_end4) ? sv : zv;
        }
    } else {
        // ---- counts + ballot cache: warp per (center,chunk) ----
        int warp = (int)((((size_t)blockIdx.x - FB) * blockDim.x + threadIdx.x) >> 5);
        int lane = threadIdx.x & 31;
        if (warp >= N * C) return;
        int k = warp / C;
        int c = warp - k * C;

        const float* pk = pos + 3 * (size_t)k;
        float xk = __ldg(pk), yk = __ldg(pk + 1), zk = __ldg(pk + 2);

        int cnt = 0;
        int tbase = c * CHUNK;
#pragma unroll 4
        for (int u = 0; u < MPW; u++) {
            int t = tbase + u * 32 + lane;
            bool valid = false;
            if (t > 0 && t < N) {
                int j = k + t;
                if (j >= N) j -= N;
                const float* pj = pos + 3 * (size_t)j;
                float dx = __fsub_rn(__ldg(pj),     xk);
                float dy = __fsub_rn(__ldg(pj + 1), yk);
                float dz = __fsub_rn(__ldg(pj + 2), zk);
                valid = dist2(dx, dy, dz) < 25.0f;
            }
            unsigned m = __ballot_sync(0xffffffffu, valid);
            if (lane == 0) g_masks[warp * MPW + u] = m;
            cnt += __popc(m);
        }
        if (lane == 0) g_counts[warp] = cnt;
    }
}

// -------- Kernel 2: prefetched register scan (1 block, 1024 thr) ----------
__global__ __launch_bounds__(1024) void scan_kernel(float* __restrict__ out,
                                                    size_t M, int S) {
    __shared__ int wsum[32];
    __shared__ int wbase[32];
    __shared__ int tile_tot[NTILES];
    int t = threadIdx.x;
    int warp = t >> 5, lane = t & 31;

    // prefetch ALL counts (coalesced, independent -> single latency exposure)
    int c[NTILES];
#pragma unroll
    for (int u = 0; u < NTILES; u++) {
        int i = u * 1024 + t;
        c[u] = (i < S) ? g_counts[i] : 0;
    }

    int excl[NTILES];  // exclusive offset within tile
#pragma unroll
    for (int u = 0; u < NTILES; u++) {
        int incl = c[u];
#pragma unroll
        for (int o = 1; o < 32; o <<= 1) {
            int v = __shfl_up_sync(0xffffffffu, incl, o);
            if (lane >= o) incl += v;
        }
        if (lane == 31) wsum[warp] = incl;
        __syncthreads();
        if (warp == 0) {
            int v = wsum[lane];
            int winc = v;
#pragma unroll
            for (int o = 1; o < 32; o <<= 1) {
                int x = __shfl_up_sync(0xffffffffu, winc, o);
                if (lane >= o) winc += x;
            }
            wbase[lane] = winc - v;
            if (lane == 31) tile_tot[u] = winc;
        }
        __syncthreads();
        excl[u] = wbase[warp] + (incl - c[u]);
    }

    // accumulate tile totals (same value computed by all threads)
    int running = 0;
#pragma unroll
    for (int u = 0; u < NTILES; u++) {
        int i = u * 1024 + t;
        if (i < S) g_offsets[i] = running + excl[u];
        running += tile_tot[u];
    }
    if (t == 0) {
        g_total = running;
        out[9 * M] = (float)running;  // num_pairs
    }
}

// -------- Kernel 3: thread-per-valid-pair emit ----------------------------
__global__ __launch_bounds__(256) void emit_kernel(const float* __restrict__ pos,
                                                   float* __restrict__ out,
                                                   size_t M, int N, int C, int S) {
    int T = g_total;
    float* __restrict__ idx_i = out;
    float* __restrict__ idx_j = out + M;
    float* __restrict__ rij   = out + 2 * M;
    float* __restrict__ maskp = out + 8 * M;

    int stride = (int)(gridDim.x * blockDim.x);
    for (int p = (int)(blockIdx.x * blockDim.x + threadIdx.x); p < T;
         p += stride) {
        // binary search: largest w with g_offsets[w] <= p
        int lo = 0, hi = S;
        while (hi - lo > 1) {
            int mid = (lo + hi) >> 1;
            if (g_offsets[mid] <= p) lo = mid; else hi = mid;
        }
        int w = lo;
        int r = p - g_offsets[w];          // rank within segment
        int k = w / C;
        int c = w - k * C;

        // locate the ballot containing rank r
        int u = 0;
        unsigned m;
        for (;;) {
            m = g_masks[w * MPW + u];
            int cnt = __popc(m);
            if (r < cnt) break;
            r -= cnt;
            u++;
        }
        // r-th set bit of m
        unsigned mm = m;
        for (int q = 0; q < r; q++) mm &= mm - 1;
        int lane = __ffs(mm) - 1;

        int t = c * CHUNK + u * 32 + lane;
        int j = k + t;
        if (j >= N) j -= N;

        const float* pk = pos + 3 * (size_t)k;
        const float* pj = pos + 3 * (size_t)j;
        float dx = __fsub_rn(__ldg(pj),     __ldg(pk));      // pos[j]-pos[k]
        float dy = __fsub_rn(__ldg(pj + 1), __ldg(pk + 1));
        float dz = __fsub_rn(__ldg(pj + 2), __ldg(pk + 2));

        idx_i[p] = (float)k;
        idx_j[p] = (float)j;
        rij[3 * (size_t)p + 0] = dx;
        rij[3 * (size_t)p + 1] = dy;
        rij[3 * (size_t)p + 2] = dz;
        maskp[p] = 1.0f;
    }
}

// ---------------------------------------------------------------------------
extern "C" void kernel_launch(void* const* d_in, const int* in_sizes, int n_in,
                              void* d_out, int out_size) {
    const float* pos = (const float*)d_in[0];
    int N = in_sizes[0] / 3;                   // 4096
    size_t M = ((size_t)out_size - 1) / 9;     // 2P = N*(N-1)
    float* out = (float*)d_out;

    int C = (N + CHUNK - 1) / CHUNK;           // 8 chunks per center
    int S = N * C;                             // 32768 segments

    int count_blocks = (S * 32 + 255) / 256;   // 4096: warp per segment
    int fill_blocks  = 4736;                   // fill first -> starts in wave 1

    fill_count_kernel<<<fill_blocks + count_blocks, 256>>>(pos, out, M, N, C,
                                                           fill_blocks);
    scan_kernel<<<1, 1024>>>(out, M, S);
    emit_kernel<<<2048, 256>>>(pos, out, M, N, C, S);
}